// round 15
// baseline (speedup 1.0000x reference)
#include <cuda_runtime.h>
#include <cuda_fp16.h>
#include <math.h>
#include <cstdint>

#define BSZ 128
#define NTREE 4095
#define NT 512

// ---- fused d10+d9 kernel smem layout
#define FA_OFF 0            // A tile 32KB (128 rows x 256B swizzled)
#define FCB_OFF 32768       // leaf c-buf 128 x 272B
#define A9_OFF 67584        // stage-2 A tile 64 rows x 256B
#define C9_OFF 83968        // stage-2 c-buf 64 x 272B (interleaved uint2)
#define FB_OFF 101376       // B frags 80KB
#define FIDX_OFF 183296     // idx: 2 slots x 1536B
#define SMEM_F 186368

// ---- top kernel smem layout
#define BUF_SZ 67584
#define CB_OFF 32768
#define CSTRIDE 272
#define B_OFF 135168
#define IDX_OFF 217088
#define SMEM_TOTAL 219136

__device__ __half g_h[2][(size_t)BSZ * 2048 * 64];
__device__ __half g_c[2][(size_t)BSZ * 2048 * 64];
__device__ uint32_t g_Bfrag[20480];   // f16x2 fragment-ordered U
__device__ uint32_t g_Wxb[20480];     // f16x2 Wx table [idx][g][colpair]
__device__ uint32_t g_leafh[4096];    // f16x2 leaf h table [idx][colpair]
__device__ uint32_t g_leafc[4096];    // f16x2 leaf c table [idx][colpair]

__device__ __forceinline__ uint32_t smem_u32(const void* p) {
    uint32_t a;
    asm("{ .reg .u64 t; cvta.to.shared.u64 t, %1; cvt.u32.u64 %0, t; }" : "=r"(a) : "l"(p));
    return a;
}
__device__ __forceinline__ __half2 tanh2(__half2 x) {
    uint32_t r, xi = *(uint32_t*)&x;
    asm("tanh.approx.f16x2 %0, %1;" : "=r"(r) : "r"(xi));
    return *(__half2*)&r;
}
__device__ __forceinline__ __half2 sig2(__half2 x) {
    const __half2 h = __float2half2_rn(0.5f);
    return __hfma2(tanh2(__hmul2(x, h)), h, h);
}
__device__ __forceinline__ float tanhapf(float x) {
    float y;
    asm("tanh.approx.f32 %0, %1;" : "=f"(y) : "f"(x));
    return y;
}
__device__ __forceinline__ float sigapf(float x) {
    return fmaf(tanhapf(0.5f * x), 0.5f, 0.5f);
}
__device__ __forceinline__ void mma_f16(uint32_t d[2], uint32_t a0, uint32_t a1,
                                        uint32_t a2, uint32_t a3,
                                        uint32_t b0, uint32_t b1) {
    asm volatile(
        "mma.sync.aligned.m16n8k16.row.col.f16.f16.f16.f16 "
        "{%0,%1}, {%2,%3,%4,%5}, {%6,%7}, {%0,%1};"
        : "+r"(d[0]), "+r"(d[1])
        : "r"(a0), "r"(a1), "r"(a2), "r"(a3), "r"(b0), "r"(b1));
}

// ---------------- prep: U fragments + Wx f16 table + leaf h/c vocab table
__global__ void prep_kernel(const float* __restrict__ Ua, const float* __restrict__ Ub,
                            const float* __restrict__ Wx, const float* __restrict__ bt) {
    int id = blockIdx.x * blockDim.x + threadIdx.x;   // 20480
    if (id >= 20480) return;
    {   // U: [g][wn][ks][lane][j]
        int j = id & 1;
        int lane = (id >> 1) & 31;
        int ks = (id >> 6) & 7;
        int wn = (id >> 9) & 7;
        int g = id >> 12;
        int k0 = ks * 16 + (lane & 3) * 2 + j * 8;
        int n = g * 64 + wn * 8 + (lane >> 2);
        float v0 = (k0 < 64) ? Ua[k0 * 320 + n] : Ub[(k0 - 64) * 320 + n];
        float v1 = (k0 + 1 < 64) ? Ua[(k0 + 1) * 320 + n] : Ub[(k0 + 1 - 64) * 320 + n];
        __half2 p = __floats2half2_rn(v0, v1);
        g_Bfrag[id] = *(uint32_t*)&p;
    }
    {   // Wx: [idx][g][jp]
        int idx = id / 160;
        int rem = id - idx * 160;
        int g = rem >> 5, jp = rem & 31;
        const float* w = Wx + idx * 320 + g * 64 + 2 * jp;
        __half2 p = __floats2half2_rn(w[0], w[1]);
        g_Wxb[id] = *(uint32_t*)&p;
    }
    if (id < 4096) {   // leaf table: [idx][jp] -> h,c for cols (2jp, 2jp+1)
        int idx = id >> 5, jp = id & 31;
        const float* w = Wx + idx * 320;
        float h[2], c[2];
#pragma unroll
        for (int e = 0; e < 2; ++e) {
            int col = 2 * jp + e;
            float zi = w[col] + bt[col];
            float zo = w[192 + col] + bt[192 + col];
            float zu = w[256 + col] + bt[256 + col];
            c[e] = sigapf(zi) * tanhapf(zu);
            h[e] = sigapf(zo) * tanhapf(c[e]);
        }
        __half2 hp = __floats2half2_rn(h[0], h[1]);
        __half2 cp = __floats2half2_rn(c[0], c[1]);
        g_leafh[id] = *(uint32_t*)&hp;
        g_leafc[id] = *(uint32_t*)&cp;
    }
}

// ---------------- shared tile pieces
__device__ __forceinline__ void fill_a_noidx(char* smem, int abase,
                                             const __half* __restrict__ asrc) {
    int tid = threadIdx.x;
    const uint4* src = (const uint4*)asrc;
#pragma unroll
    for (int i = 0; i < 4; ++i) {
        int f = tid + i * NT;
        int row = f >> 4, c = f & 15;
        uint4 v = src[f];
        *(uint4*)(smem + abase + row * 256 + ((c ^ (row & 7)) << 4)) = v;
    }
}

// fused fill: leaf children h,c from vocab table (no MUFU); idx preload
__device__ __forceinline__ void fill_children(char* smem,
                                              const int* __restrict__ cidx,
                                              const int* __restrict__ pidx10,
                                              const int* __restrict__ pidx9,
                                              int islot) {
    int tid = threadIdx.x;
    int lane = tid & 31, w = tid >> 5;
#pragma unroll
    for (int it = 0; it < 16; ++it) {
        int child = w + it * 16;
        int idx = cidx[child];
        uint32_t h2 = g_leafh[idx * 32 + lane];
        uint32_t c2 = g_leafc[idx * 32 + lane];
        int row = child >> 1, side = child & 1;
        int chunk = side * 8 + (lane >> 2);
        int aaddr = FA_OFF + row * 256 + ((chunk ^ (row & 7)) << 4) + (lane & 3) * 4;
        *(uint32_t*)(smem + aaddr) = h2;
        *(uint32_t*)(smem + FCB_OFF + row * CSTRIDE + side * 128 + lane * 4) = c2;
    }
    int* ib = (int*)(smem + FIDX_OFF + islot * 1536);
    if (tid < 128) ib[tid] = pidx10[tid];
    else if (tid < 192) ib[128 + (tid - 128)] = pidx9[tid - 128];
}

__device__ __forceinline__ void do_mma(char* smem, uint32_t sA, uint32_t acc[4][5][2],
                                       int nvalid, int wm, int wn, int lane, int boff) {
    if (wm * 64 >= nvalid) return;
    const int row_local = (lane & 7) | (((lane >> 3) & 1) << 3);
    const int hi = (lane >> 4) & 1;
#pragma unroll
    for (int ks = 0; ks < 8; ++ks) {
        uint2 bf[5];
#pragma unroll
        for (int g = 0; g < 5; ++g)
            bf[g] = *(const uint2*)(smem + boff + ((((g * 8 + wn) * 8 + ks) * 32 + lane) << 3));
        int c = ks * 2 + hi;
#pragma unroll
        for (int mfl = 0; mfl < 4; ++mfl) {
            int mf = wm * 4 + mfl;
            if (mf * 16 < nvalid) {
                uint32_t addr = sA + (mf * 16 + row_local) * 256 + ((c ^ (lane & 7)) << 4);
                uint32_t a0, a1, a2, a3;
                asm volatile("ldmatrix.sync.aligned.m8n8.x4.shared.b16 {%0,%1,%2,%3}, [%4];"
                             : "=r"(a0), "=r"(a1), "=r"(a2), "=r"(a3) : "r"(addr));
#pragma unroll
                for (int g = 0; g < 5; ++g)
                    mma_f16(acc[mfl][g], a0, a1, a2, a3, bf[g].x, bf[g].y);
            }
        }
    }
}

__device__ __forceinline__ void gates(const __half2 z[5], __half2 ca, __half2 cb,
                                      __half2& hn, __half2& cn) {
    cn = __hfma2(sig2(z[1]), ca,
          __hfma2(sig2(z[2]), cb,
           __hmul2(sig2(z[0]), tanh2(z[4]))));
    hn = __hmul2(sig2(z[3]), tanh2(cn));
}

// fused d10 epilogue: c from leaf cbuf; out -> smem A9 (swizzled) + c9 (interleaved)
__device__ __forceinline__ void epi10s(char* smem, int islot, uint32_t acc[4][5][2],
                                       const __half2 bb2[5], int wm, int jp, int lane) {
    const int* idx10 = (const int*)(smem + FIDX_OFF + islot * 1536);
#pragma unroll
    for (int mfl = 0; mfl < 4; ++mfl) {
#pragma unroll
        for (int half = 0; half < 2; ++half) {
            int rloc = wm * 64 + mfl * 16 + half * 8 + (lane >> 2);
            int idx = idx10[rloc];
            const __half2* w = (const __half2*)g_Wxb + idx * 160 + jp;
            __half2 z[5];
#pragma unroll
            for (int g = 0; g < 5; ++g)
                z[g] = __hadd2(__hadd2(*(__half2*)&acc[mfl][g][half], w[g * 32]), bb2[g]);
            __half2 ca = *(const __half2*)(smem + FCB_OFF + rloc * CSTRIDE + jp * 4);
            __half2 cb = *(const __half2*)(smem + FCB_OFF + rloc * CSTRIDE + 128 + jp * 4);
            __half2 hn, cn;
            gates(z, ca, cb, hn, cn);
            int orow = rloc >> 1, side = rloc & 1;
            int chunk = (side * 8 + (jp >> 2)) ^ (orow & 7);
            *(uint32_t*)(smem + A9_OFF + orow * 256 + (chunk << 4) + (jp & 3) * 4) =
                *(uint32_t*)&hn;
            *(uint32_t*)(smem + C9_OFF + orow * CSTRIDE + jp * 8 + side * 4) =
                *(uint32_t*)&cn;
        }
    }
}

// fused d9 epilogue: c from smem c9 (interleaved); out -> gmem d9 state
__device__ __forceinline__ void epi9g(char* smem, int islot, uint32_t acc[4][5][2],
                                      __half* __restrict__ houtp,
                                      __half* __restrict__ coutp,
                                      const __half2 bb2[5], int wm, int jp, int lane) {
    const int* idx9 = (const int*)(smem + FIDX_OFF + islot * 1536) + 128;
#pragma unroll
    for (int mfl = 0; mfl < 4; ++mfl) {
#pragma unroll
        for (int half = 0; half < 2; ++half) {
            int rloc = wm * 64 + mfl * 16 + half * 8 + (lane >> 2);
            if (rloc < 64) {
                int idx = idx9[rloc];
                const __half2* w = (const __half2*)g_Wxb + idx * 160 + jp;
                __half2 z[5];
#pragma unroll
                for (int g = 0; g < 5; ++g)
                    z[g] = __hadd2(__hadd2(*(__half2*)&acc[mfl][g][half], w[g * 32]), bb2[g]);
                uint2 v = *(const uint2*)(smem + C9_OFF + rloc * CSTRIDE + jp * 8);
                __half2 ca = *(__half2*)&v.x;
                __half2 cb = *(__half2*)&v.y;
                __half2 hn, cn;
                gates(z, ca, cb, hn, cn);
                *(uint32_t*)(houtp + (size_t)rloc * 64 + 2 * jp) = *(uint32_t*)&hn;
                *(uint32_t*)(coutp + (size_t)rloc * 64 + 2 * jp) = *(uint32_t*)&cn;
            }
        }
    }
}

// top epilogue with PREFETCHED Wx: out -> next-level smem A + cbuf
__device__ __forceinline__ void epi_top_pre(char* smem, const uint32_t wpre[8][5],
                                            uint32_t acc[4][5][2], int nvalid,
                                            const __half* __restrict__ csrc, int cbin,
                                            int outbase, int orow_off,
                                            const __half2 bb2[5], int wm, int jp, int lane) {
#pragma unroll
    for (int mfl = 0; mfl < 4; ++mfl) {
#pragma unroll
        for (int half = 0; half < 2; ++half) {
            int rloc = wm * 64 + mfl * 16 + half * 8 + (lane >> 2);
            if (rloc < nvalid) {
                __half2 z[5];
#pragma unroll
                for (int g = 0; g < 5; ++g) {
                    uint32_t wv = wpre[mfl * 2 + half][g];
                    z[g] = __hadd2(__hadd2(*(__half2*)&acc[mfl][g][half], *(__half2*)&wv),
                                   bb2[g]);
                }
                __half2 ca, cb;
                if (csrc) {
                    ca = *(const __half2*)(csrc + (size_t)rloc * 128 + 2 * jp);
                    cb = *(const __half2*)(csrc + (size_t)rloc * 128 + 64 + 2 * jp);
                } else {
                    uint2 v = *(const uint2*)(smem + cbin + rloc * CSTRIDE + jp * 8);
                    ca = *(__half2*)&v.x;
                    cb = *(__half2*)&v.y;
                }
                __half2 hn, cn;
                gates(z, ca, cb, hn, cn);
                int orow = orow_off + (rloc >> 1);
                int side = rloc & 1;
                int chunk = (side * 8 + (jp >> 2)) ^ (orow & 7);
                *(uint32_t*)(smem + outbase + orow * 256 + (chunk << 4) + (jp & 3) * 4) =
                    *(uint32_t*)&hn;
                *(uint32_t*)(smem + outbase + CB_OFF + orow * CSTRIDE + jp * 8 + side * 4) =
                    *(uint32_t*)&cn;
            }
        }
    }
}

// prefetch Wx rows for a level's epilogue (idx already in smem sidx)
__device__ __forceinline__ void wx_prefetch(const int* __restrict__ lidx, int nvalid,
                                            uint32_t wpre[8][5], int wm, int jp, int lane) {
#pragma unroll
    for (int mfl = 0; mfl < 4; ++mfl) {
#pragma unroll
        for (int half = 0; half < 2; ++half) {
            int rloc = wm * 64 + mfl * 16 + half * 8 + (lane >> 2);
            if (rloc < nvalid) {
                int idx = lidx[rloc];
                const uint32_t* w = g_Wxb + idx * 160 + jp;
#pragma unroll
                for (int g = 0; g < 5; ++g) wpre[mfl * 2 + half][g] = w[g * 32];
            }
        }
    }
}

__device__ __forceinline__ void load_common(char* smem, const float* bt, __half2 bb2[5],
                                            int jp, int boff) {
    int tid = threadIdx.x;
    const uint4* src = (const uint4*)g_Bfrag;
    uint4* dst = (uint4*)(smem + boff);
#pragma unroll
    for (int i = 0; i < 10; ++i) dst[tid + i * NT] = src[tid + i * NT];
#pragma unroll
    for (int g = 0; g < 5; ++g) {
        float2 bv = *(const float2*)(bt + g * 64 + 2 * jp);
        bb2[g] = __floats2half2_rn(bv.x, bv.y);
    }
}

// ---------------- fused leaf + d10 + d9, pipelined fill (round-13, unchanged)
__global__ void __launch_bounds__(NT, 1)
level109(const int* __restrict__ x_idx, const float* __restrict__ bt) {
    extern __shared__ char smem[];
    uint32_t sb = smem_u32(smem);
    const int tid = threadIdx.x;
    const int lane = tid & 31, wid = tid >> 5;
    const int wm = wid >> 3, wn = wid & 7;
    const int jp = wn * 4 + (lane & 3);
    __half2 bb2[5];
    load_common(smem, bt, bb2, jp, FB_OFF);
    __half* ho = g_h[1];
    __half* co = g_c[1];
    const int step = gridDim.x;
    int q = 0;
    int t = blockIdx.x;
    if (t < 1024) {
        int m0 = t << 7, b = m0 >> 10, jl0 = m0 & 1023;
        fill_children(smem, x_idx + b * NTREE + 2047 + 2 * jl0,
                      x_idx + b * NTREE + 1023 + jl0,
                      x_idx + b * NTREE + 511 + (jl0 >> 1), 0);
    }
    __syncthreads();
    for (; t < 1024; t += step) {
        int m0 = t << 7, b = m0 >> 10, jl0 = m0 & 1023;
        uint32_t acc[4][5][2] = {};
        do_mma(smem, sb + FA_OFF, acc, 128, wm, wn, lane, FB_OFF);
        epi10s(smem, q, acc, bb2, wm, jp, lane);
        __syncthreads();
        uint32_t acc9[4][5][2] = {};
        do_mma(smem, sb + A9_OFF, acc9, 64, wm, wn, lane, FB_OFF);
        int nt = t + step;
        if (nt < 1024) {
            int m1 = nt << 7, b1 = m1 >> 10, jl1 = m1 & 1023;
            fill_children(smem, x_idx + b1 * NTREE + 2047 + 2 * jl1,
                          x_idx + b1 * NTREE + 1023 + jl1,
                          x_idx + b1 * NTREE + 511 + (jl1 >> 1), q ^ 1);
        }
        int j0 = b * 512 + (jl0 >> 1);
        epi9g(smem, q, acc9, ho + (size_t)j0 * 64, co + (size_t)j0 * 64,
              bb2, wm, jp, lane);
        __syncthreads();
        q ^= 1;
    }
}

// ---------------- fused top levels d = 8..0 + head, Wx prefetched per level
__global__ void __launch_bounds__(NT, 1)
top_mma(const int* __restrict__ x_idx, const float* __restrict__ bt,
        const float* __restrict__ W1, const float* __restrict__ b1,
        const float* __restrict__ W2, const float* __restrict__ b2,
        const float* __restrict__ W_ih, const float* __restrict__ b_lstm,
        const float* __restrict__ actorW, const float* __restrict__ actorb,
        const float* __restrict__ vm, float* __restrict__ out) {
    extern __shared__ char smem[];
    uint32_t sb = smem_u32(smem);
    const int tid = threadIdx.x;
    const int lane = tid & 31, wid = tid >> 5;
    const int wm = wid >> 3, wn = wid & 7;
    const int jp = wn * 4 + (lane & 3);
    __half2 bb2[5];
    load_common(smem, bt, bb2, jp, B_OFF);
    int* sidx = (int*)(smem + IDX_OFF);
    const int b = blockIdx.x;
    if (tid < 511) sidx[tid] = x_idx[b * NTREE + tid];

    // ---- d = 8: two 128-row tiles from gmem d9 state; out -> smem buf1
    fill_a_noidx(smem, 0, g_h[1] + (size_t)b * 512 * 64);
    __syncthreads();
#pragma unroll
    for (int tt = 0; tt < 2; ++tt) {
        uint32_t wpre[8][5];
        wx_prefetch(sidx + 255 + tt * 128, 128, wpre, wm, jp, lane);
        uint32_t acc[4][5][2] = {};
        do_mma(smem, sb, acc, 128, wm, wn, lane, B_OFF);
        __syncthreads();
        if (tt == 0)
            fill_a_noidx(smem, 0, g_h[1] + (size_t)(b * 512 + 256) * 64);
        epi_top_pre(smem, wpre, acc, 128,
                    g_c[1] + (size_t)(b * 512 + tt * 256) * 64,
                    0, BUF_SZ, tt * 64, bb2, wm, jp, lane);
        __syncthreads();
    }

    // ---- levels 7..0, smem-resident
    int p = 1;
#pragma unroll
    for (int d = 7; d >= 0; --d) {
        int n = 1 << d;
        uint32_t wpre[8][5];
        wx_prefetch(sidx + (n - 1), n, wpre, wm, jp, lane);
        uint32_t acc[4][5][2] = {};
        do_mma(smem, sb + p * BUF_SZ, acc, n, wm, wn, lane, B_OFF);
        epi_top_pre(smem, wpre, acc, n, (const __half*)0,
                    p * BUF_SZ + CB_OFF, (p ^ 1) * BUF_SZ, 0, bb2, wm, jp, lane);
        __syncthreads();
        p ^= 1;
    }
    // root h in buf0 A row 0 (contiguous 64 halves)

    // ---- head (scratch in buf1, dead)
    float* sh = (float*)(smem + BUF_SZ);
    float* sf1 = sh + 64;
    float* sfeat = sf1 + 64;
    float* slog = sfeat + 128;
    float* sinv = slog + 20;
    const __half* hroot = (const __half*)smem;
    int t = tid;
    if (t < 64) sh[t] = __half2float(hroot[t]);
    __syncthreads();
    if (t < 64) {
        float a = 0.f;
        for (int k = 0; k < 64; ++k) a += sh[k] * W1[k * 64 + t];
        sf1[t] = fmaxf(a + b1[t], 0.f);
    }
    __syncthreads();
    if (t < 64) {
        float f = 0.f;
        for (int k = 0; k < 64; ++k) f += sf1[k] * W2[k * 64 + t];
        sfeat[t] = f + b2[t];
    }
    __syncthreads();
    if (t < 64) {
        float gi = 0.f, gg = 0.f, go = 0.f;
        for (int k = 0; k < 64; ++k) {
            float fk = sfeat[k];
            gi += fk * W_ih[k * 256 + t];
            gg += fk * W_ih[k * 256 + 128 + t];
            go += fk * W_ih[k * 256 + 192 + t];
        }
        gi += b_lstm[t];
        gg += b_lstm[128 + t];
        go += b_lstm[192 + t];
        float cg = (1.f / (1.f + expf(-gi))) * tanhf(gg);
        sfeat[64 + t] = (1.f / (1.f + expf(-go))) * tanhf(cg);
    }
    __syncthreads();
    if (t < 20) {
        float l = 0.f;
        for (int dd = 0; dd < 128; ++dd) l += sfeat[dd] * actorW[dd * 20 + t];
        l = logf(vm[t]) + l * vm[t] + actorb[t] * vm[t];
        slog[t] = l / 3.0f;
    }
    __syncthreads();
    if (t == 0) {
        float mx = slog[0];
        for (int k = 1; k < 20; ++k) mx = fmaxf(mx, slog[k]);
        float s = 0.f;
        for (int k = 0; k < 20; ++k) {
            float e = expf(slog[k] - mx);
            slog[k] = e;
            s += e;
        }
        sinv[0] = 1.f / s;
    }
    __syncthreads();
    if (t < 20) out[b * 20 + t] = slog[t] * sinv[0];
}

extern "C" void kernel_launch(void* const* d_in, const int* in_sizes, int n_in,
                              void* d_out, int out_size) {
    const int*   x_idx  = (const int*)d_in[0];
    const float* vm     = (const float*)d_in[1];
    const float* Wx     = (const float*)d_in[2];
    const float* Ua     = (const float*)d_in[3];
    const float* Ub     = (const float*)d_in[4];
    const float* bt     = (const float*)d_in[5];
    const float* W_ih   = (const float*)d_in[6];
    const float* b_lstm = (const float*)d_in[8];
    const float* W1     = (const float*)d_in[9];
    const float* b1     = (const float*)d_in[10];
    const float* W2     = (const float*)d_in[11];
    const float* b2     = (const float*)d_in[12];
    const float* actorW = (const float*)d_in[13];
    const float* actorb = (const float*)d_in[14];
    float* out = (float*)d_out;

    cudaFuncSetAttribute(level109, cudaFuncAttributeMaxDynamicSharedMemorySize, SMEM_F);
    cudaFuncSetAttribute(top_mma, cudaFuncAttributeMaxDynamicSharedMemorySize, SMEM_TOTAL);

    prep_kernel<<<80, 256>>>(Ua, Ub, Wx, bt);
    level109<<<152, NT, SMEM_F>>>(x_idx, bt);
    top_mma<<<BSZ, NT, SMEM_TOTAL>>>(x_idx, bt, W1, b1, W2, b2, W_ih, b_lstm,
                                     actorW, actorb, vm, out);
}

// round 16
// speedup vs baseline: 1.6438x; 1.6438x over previous
#include <cuda_runtime.h>
#include <cuda_fp16.h>
#include <math.h>
#include <cstdint>

#define BSZ 128
#define NTREE 4095
#define NT 512

// ---- fused d10+d9 kernel smem layout
#define FA_OFF 0            // A tile 32KB (128 rows x 256B swizzled)
#define FCB_OFF 32768       // leaf c-buf 128 x 272B
#define A9_OFF 67584        // stage-2 A tile 64 rows x 256B
#define C9_OFF 83968        // stage-2 c-buf 64 x 272B (interleaved uint2)
#define FB_OFF 101376       // B frags 80KB
#define FIDX_OFF 183296     // idx: 2 slots x 1536B
#define SMEM_F 186368

// ---- top kernel smem layout
#define BUF_SZ 67584
#define CB_OFF 32768
#define CSTRIDE 272
#define B_OFF 135168
#define IDX_OFF 217088
#define SMEM_TOTAL 219136

__device__ __half g_h[2][(size_t)BSZ * 2048 * 64];
__device__ __half g_c[2][(size_t)BSZ * 2048 * 64];
__device__ uint32_t g_Bfrag[20480];   // f16x2 fragment-ordered U
__device__ uint32_t g_Wxb[20480];     // f16x2 Wx table [idx][g][colpair]
__device__ uint32_t g_leafh[4096];    // f16x2 leaf h table [idx][colpair]
__device__ uint32_t g_leafc[4096];    // f16x2 leaf c table [idx][colpair]

__device__ __forceinline__ uint32_t smem_u32(const void* p) {
    uint32_t a;
    asm("{ .reg .u64 t; cvta.to.shared.u64 t, %1; cvt.u32.u64 %0, t; }" : "=r"(a) : "l"(p));
    return a;
}
__device__ __forceinline__ __half2 tanh2(__half2 x) {
    uint32_t r, xi = *(uint32_t*)&x;
    asm("tanh.approx.f16x2 %0, %1;" : "=r"(r) : "r"(xi));
    return *(__half2*)&r;
}
__device__ __forceinline__ __half2 sig2(__half2 x) {
    const __half2 h = __float2half2_rn(0.5f);
    return __hfma2(tanh2(__hmul2(x, h)), h, h);
}
__device__ __forceinline__ float tanhapf(float x) {
    float y;
    asm("tanh.approx.f32 %0, %1;" : "=f"(y) : "f"(x));
    return y;
}
__device__ __forceinline__ float sigapf(float x) {
    return fmaf(tanhapf(0.5f * x), 0.5f, 0.5f);
}
__device__ __forceinline__ void mma_f16(uint32_t d[2], uint32_t a0, uint32_t a1,
                                        uint32_t a2, uint32_t a3,
                                        uint32_t b0, uint32_t b1) {
    asm volatile(
        "mma.sync.aligned.m16n8k16.row.col.f16.f16.f16.f16 "
        "{%0,%1}, {%2,%3,%4,%5}, {%6,%7}, {%0,%1};"
        : "+r"(d[0]), "+r"(d[1])
        : "r"(a0), "r"(a1), "r"(a2), "r"(a3), "r"(b0), "r"(b1));
}

// ---------------- prep: U fragments + Wx f16 table + leaf h/c vocab table
__global__ void prep_kernel(const float* __restrict__ Ua, const float* __restrict__ Ub,
                            const float* __restrict__ Wx, const float* __restrict__ bt) {
    int id = blockIdx.x * blockDim.x + threadIdx.x;   // 20480
    if (id >= 20480) return;
    {   // U: [g][wn][ks][lane][j]
        int j = id & 1;
        int lane = (id >> 1) & 31;
        int ks = (id >> 6) & 7;
        int wn = (id >> 9) & 7;
        int g = id >> 12;
        int k0 = ks * 16 + (lane & 3) * 2 + j * 8;
        int n = g * 64 + wn * 8 + (lane >> 2);
        float v0 = (k0 < 64) ? Ua[k0 * 320 + n] : Ub[(k0 - 64) * 320 + n];
        float v1 = (k0 + 1 < 64) ? Ua[(k0 + 1) * 320 + n] : Ub[(k0 + 1 - 64) * 320 + n];
        __half2 p = __floats2half2_rn(v0, v1);
        g_Bfrag[id] = *(uint32_t*)&p;
    }
    {   // Wx: [idx][g][jp]
        int idx = id / 160;
        int rem = id - idx * 160;
        int g = rem >> 5, jp = rem & 31;
        const float* w = Wx + idx * 320 + g * 64 + 2 * jp;
        __half2 p = __floats2half2_rn(w[0], w[1]);
        g_Wxb[id] = *(uint32_t*)&p;
    }
    if (id < 4096) {   // leaf table: [idx][jp] -> h,c for cols (2jp, 2jp+1)
        int idx = id >> 5, jp = id & 31;
        const float* w = Wx + idx * 320;
        float h[2], c[2];
#pragma unroll
        for (int e = 0; e < 2; ++e) {
            int col = 2 * jp + e;
            float zi = w[col] + bt[col];
            float zo = w[192 + col] + bt[192 + col];
            float zu = w[256 + col] + bt[256 + col];
            c[e] = sigapf(zi) * tanhapf(zu);
            h[e] = sigapf(zo) * tanhapf(c[e]);
        }
        __half2 hp = __floats2half2_rn(h[0], h[1]);
        __half2 cp = __floats2half2_rn(c[0], c[1]);
        g_leafh[id] = *(uint32_t*)&hp;
        g_leafc[id] = *(uint32_t*)&cp;
    }
}

// ---------------- shared tile pieces
__device__ __forceinline__ void fill_a_noidx(char* smem, int abase,
                                             const __half* __restrict__ asrc) {
    int tid = threadIdx.x;
    const uint4* src = (const uint4*)asrc;
#pragma unroll
    for (int i = 0; i < 4; ++i) {
        int f = tid + i * NT;
        int row = f >> 4, c = f & 15;
        uint4 v = src[f];
        *(uint4*)(smem + abase + row * 256 + ((c ^ (row & 7)) << 4)) = v;
    }
}

// fused fill: leaf children h,c from vocab table (no MUFU); idx preload
__device__ __forceinline__ void fill_children(char* smem,
                                              const int* __restrict__ cidx,
                                              const int* __restrict__ pidx10,
                                              const int* __restrict__ pidx9,
                                              int islot) {
    int tid = threadIdx.x;
    int lane = tid & 31, w = tid >> 5;
#pragma unroll
    for (int it = 0; it < 16; ++it) {
        int child = w + it * 16;
        int idx = cidx[child];
        uint32_t h2 = g_leafh[idx * 32 + lane];
        uint32_t c2 = g_leafc[idx * 32 + lane];
        int row = child >> 1, side = child & 1;
        int chunk = side * 8 + (lane >> 2);
        int aaddr = FA_OFF + row * 256 + ((chunk ^ (row & 7)) << 4) + (lane & 3) * 4;
        *(uint32_t*)(smem + aaddr) = h2;
        *(uint32_t*)(smem + FCB_OFF + row * CSTRIDE + side * 128 + lane * 4) = c2;
    }
    int* ib = (int*)(smem + FIDX_OFF + islot * 1536);
    if (tid < 128) ib[tid] = pidx10[tid];
    else if (tid < 192) ib[128 + (tid - 128)] = pidx9[tid - 128];
}

__device__ __forceinline__ void do_mma(char* smem, uint32_t sA, uint32_t acc[4][5][2],
                                       int nvalid, int wm, int wn, int lane, int boff) {
    if (wm * 64 >= nvalid) return;
    const int row_local = (lane & 7) | (((lane >> 3) & 1) << 3);
    const int hi = (lane >> 4) & 1;
#pragma unroll
    for (int ks = 0; ks < 8; ++ks) {
        uint2 bf[5];
#pragma unroll
        for (int g = 0; g < 5; ++g)
            bf[g] = *(const uint2*)(smem + boff + ((((g * 8 + wn) * 8 + ks) * 32 + lane) << 3));
        int c = ks * 2 + hi;
#pragma unroll
        for (int mfl = 0; mfl < 4; ++mfl) {
            int mf = wm * 4 + mfl;
            if (mf * 16 < nvalid) {
                uint32_t addr = sA + (mf * 16 + row_local) * 256 + ((c ^ (lane & 7)) << 4);
                uint32_t a0, a1, a2, a3;
                asm volatile("ldmatrix.sync.aligned.m8n8.x4.shared.b16 {%0,%1,%2,%3}, [%4];"
                             : "=r"(a0), "=r"(a1), "=r"(a2), "=r"(a3) : "r"(addr));
#pragma unroll
                for (int g = 0; g < 5; ++g)
                    mma_f16(acc[mfl][g], a0, a1, a2, a3, bf[g].x, bf[g].y);
            }
        }
    }
}

// stage-2 mma over 64 rows using ALL 16 warps: warp (wm,wn) -> rows [wm*32,+32)
__device__ __forceinline__ void do_mma9(char* smem, uint32_t sA, uint32_t acc[2][5][2],
                                        int wm, int wn, int lane, int boff) {
    const int row_local = (lane & 7) | (((lane >> 3) & 1) << 3);
    const int hi = (lane >> 4) & 1;
#pragma unroll
    for (int ks = 0; ks < 8; ++ks) {
        uint2 bf[5];
#pragma unroll
        for (int g = 0; g < 5; ++g)
            bf[g] = *(const uint2*)(smem + boff + ((((g * 8 + wn) * 8 + ks) * 32 + lane) << 3));
        int c = ks * 2 + hi;
#pragma unroll
        for (int mfl = 0; mfl < 2; ++mfl) {
            int mf = wm * 2 + mfl;
            uint32_t addr = sA + (mf * 16 + row_local) * 256 + ((c ^ (lane & 7)) << 4);
            uint32_t a0, a1, a2, a3;
            asm volatile("ldmatrix.sync.aligned.m8n8.x4.shared.b16 {%0,%1,%2,%3}, [%4];"
                         : "=r"(a0), "=r"(a1), "=r"(a2), "=r"(a3) : "r"(addr));
#pragma unroll
            for (int g = 0; g < 5; ++g)
                mma_f16(acc[mfl][g], a0, a1, a2, a3, bf[g].x, bf[g].y);
        }
    }
}

__device__ __forceinline__ void gates(const __half2 z[5], __half2 ca, __half2 cb,
                                      __half2& hn, __half2& cn) {
    cn = __hfma2(sig2(z[1]), ca,
          __hfma2(sig2(z[2]), cb,
           __hmul2(sig2(z[0]), tanh2(z[4]))));
    hn = __hmul2(sig2(z[3]), tanh2(cn));
}

// fused d10 epilogue: c from leaf cbuf; out -> smem A9 (swizzled) + c9 (interleaved)
__device__ __forceinline__ void epi10s(char* smem, int islot, uint32_t acc[4][5][2],
                                       const __half2 bb2[5], int wm, int jp, int lane) {
    const int* idx10 = (const int*)(smem + FIDX_OFF + islot * 1536);
#pragma unroll
    for (int mfl = 0; mfl < 4; ++mfl) {
#pragma unroll
        for (int half = 0; half < 2; ++half) {
            int rloc = wm * 64 + mfl * 16 + half * 8 + (lane >> 2);
            int idx = idx10[rloc];
            const __half2* w = (const __half2*)g_Wxb + idx * 160 + jp;
            __half2 z[5];
#pragma unroll
            for (int g = 0; g < 5; ++g)
                z[g] = __hadd2(__hadd2(*(__half2*)&acc[mfl][g][half], w[g * 32]), bb2[g]);
            __half2 ca = *(const __half2*)(smem + FCB_OFF + rloc * CSTRIDE + jp * 4);
            __half2 cb = *(const __half2*)(smem + FCB_OFF + rloc * CSTRIDE + 128 + jp * 4);
            __half2 hn, cn;
            gates(z, ca, cb, hn, cn);
            int orow = rloc >> 1, side = rloc & 1;
            int chunk = (side * 8 + (jp >> 2)) ^ (orow & 7);
            *(uint32_t*)(smem + A9_OFF + orow * 256 + (chunk << 4) + (jp & 3) * 4) =
                *(uint32_t*)&hn;
            *(uint32_t*)(smem + C9_OFF + orow * CSTRIDE + jp * 8 + side * 4) =
                *(uint32_t*)&cn;
        }
    }
}

// stage-2 epilogue (16-warp split): c from smem c9; out -> gmem d9 state
__device__ __forceinline__ void epi9g2(char* smem, int islot, uint32_t acc[2][5][2],
                                       __half* __restrict__ houtp,
                                       __half* __restrict__ coutp,
                                       const __half2 bb2[5], int wm, int jp, int lane) {
    const int* idx9 = (const int*)(smem + FIDX_OFF + islot * 1536) + 128;
#pragma unroll
    for (int mfl = 0; mfl < 2; ++mfl) {
#pragma unroll
        for (int half = 0; half < 2; ++half) {
            int rloc = wm * 32 + mfl * 16 + half * 8 + (lane >> 2);
            int idx = idx9[rloc];
            const __half2* w = (const __half2*)g_Wxb + idx * 160 + jp;
            __half2 z[5];
#pragma unroll
            for (int g = 0; g < 5; ++g)
                z[g] = __hadd2(__hadd2(*(__half2*)&acc[mfl][g][half], w[g * 32]), bb2[g]);
            uint2 v = *(const uint2*)(smem + C9_OFF + rloc * CSTRIDE + jp * 8);
            __half2 ca = *(__half2*)&v.x;
            __half2 cb = *(__half2*)&v.y;
            __half2 hn, cn;
            gates(z, ca, cb, hn, cn);
            *(uint32_t*)(houtp + (size_t)rloc * 64 + 2 * jp) = *(uint32_t*)&hn;
            *(uint32_t*)(coutp + (size_t)rloc * 64 + 2 * jp) = *(uint32_t*)&cn;
        }
    }
}

// top epilogue: out -> next-level smem A + cbuf
__device__ __forceinline__ void epi_top(char* smem, const int* __restrict__ sidx,
                                        uint32_t acc[4][5][2], int nvalid,
                                        const __half* __restrict__ csrc, int cbin,
                                        int outbase, int orow_off,
                                        const __half2 bb2[5], int wm, int jp, int lane) {
#pragma unroll
    for (int mfl = 0; mfl < 4; ++mfl) {
#pragma unroll
        for (int half = 0; half < 2; ++half) {
            int rloc = wm * 64 + mfl * 16 + half * 8 + (lane >> 2);
            if (rloc < nvalid) {
                int idx = sidx[rloc];
                const __half2* w = (const __half2*)g_Wxb + idx * 160 + jp;
                __half2 z[5];
#pragma unroll
                for (int g = 0; g < 5; ++g)
                    z[g] = __hadd2(__hadd2(*(__half2*)&acc[mfl][g][half], w[g * 32]), bb2[g]);
                __half2 ca, cb;
                if (csrc) {
                    ca = *(const __half2*)(csrc + (size_t)rloc * 128 + 2 * jp);
                    cb = *(const __half2*)(csrc + (size_t)rloc * 128 + 64 + 2 * jp);
                } else {
                    uint2 v = *(const uint2*)(smem + cbin + rloc * CSTRIDE + jp * 8);
                    ca = *(__half2*)&v.x;
                    cb = *(__half2*)&v.y;
                }
                __half2 hn, cn;
                gates(z, ca, cb, hn, cn);
                int orow = orow_off + (rloc >> 1);
                int side = rloc & 1;
                int chunk = (side * 8 + (jp >> 2)) ^ (orow & 7);
                *(uint32_t*)(smem + outbase + orow * 256 + (chunk << 4) + (jp & 3) * 4) =
                    *(uint32_t*)&hn;
                *(uint32_t*)(smem + outbase + CB_OFF + orow * CSTRIDE + jp * 8 + side * 4) =
                    *(uint32_t*)&cn;
            }
        }
    }
}

__device__ __forceinline__ void load_common(char* smem, const float* bt, __half2 bb2[5],
                                            int jp, int boff) {
    int tid = threadIdx.x;
    const uint4* src = (const uint4*)g_Bfrag;
    uint4* dst = (uint4*)(smem + boff);
#pragma unroll
    for (int i = 0; i < 10; ++i) dst[tid + i * NT] = src[tid + i * NT];
#pragma unroll
    for (int g = 0; g < 5; ++g) {
        float2 bv = *(const float2*)(bt + g * 64 + 2 * jp);
        bb2[g] = __floats2half2_rn(bv.x, bv.y);
    }
}

// ---------------- fused leaf + d10 + d9, pipelined fill; stage-2 on 16 warps
__global__ void __launch_bounds__(NT, 1)
level109(const int* __restrict__ x_idx, const float* __restrict__ bt) {
    extern __shared__ char smem[];
    uint32_t sb = smem_u32(smem);
    const int tid = threadIdx.x;
    const int lane = tid & 31, wid = tid >> 5;
    const int wm = wid >> 3, wn = wid & 7;
    const int jp = wn * 4 + (lane & 3);
    __half2 bb2[5];
    load_common(smem, bt, bb2, jp, FB_OFF);
    __half* ho = g_h[1];
    __half* co = g_c[1];
    const int step = gridDim.x;
    int q = 0;
    int t = blockIdx.x;
    if (t < 1024) {
        int m0 = t << 7, b = m0 >> 10, jl0 = m0 & 1023;
        fill_children(smem, x_idx + b * NTREE + 2047 + 2 * jl0,
                      x_idx + b * NTREE + 1023 + jl0,
                      x_idx + b * NTREE + 511 + (jl0 >> 1), 0);
    }
    __syncthreads();
    for (; t < 1024; t += step) {
        int m0 = t << 7, b = m0 >> 10, jl0 = m0 & 1023;
        uint32_t acc[4][5][2] = {};
        do_mma(smem, sb + FA_OFF, acc, 128, wm, wn, lane, FB_OFF);
        epi10s(smem, q, acc, bb2, wm, jp, lane);
        __syncthreads();
        uint32_t acc9[2][5][2] = {};
        do_mma9(smem, sb + A9_OFF, acc9, wm, wn, lane, FB_OFF);
        int nt = t + step;
        if (nt < 1024) {
            int m1 = nt << 7, b1 = m1 >> 10, jl1 = m1 & 1023;
            fill_children(smem, x_idx + b1 * NTREE + 2047 + 2 * jl1,
                          x_idx + b1 * NTREE + 1023 + jl1,
                          x_idx + b1 * NTREE + 511 + (jl1 >> 1), q ^ 1);
        }
        int j0 = b * 512 + (jl0 >> 1);
        epi9g2(smem, q, acc9, ho + (size_t)j0 * 64, co + (size_t)j0 * 64,
               bb2, wm, jp, lane);
        __syncthreads();
        q ^= 1;
    }
}

// ---------------- fused top levels d = 8..0 + head (round-13, unchanged)
__global__ void __launch_bounds__(NT, 1)
top_mma(const int* __restrict__ x_idx, const float* __restrict__ bt,
        const float* __restrict__ W1, const float* __restrict__ b1,
        const float* __restrict__ W2, const float* __restrict__ b2,
        const float* __restrict__ W_ih, const float* __restrict__ b_lstm,
        const float* __restrict__ actorW, const float* __restrict__ actorb,
        const float* __restrict__ vm, float* __restrict__ out) {
    extern __shared__ char smem[];
    uint32_t sb = smem_u32(smem);
    const int tid = threadIdx.x;
    const int lane = tid & 31, wid = tid >> 5;
    const int wm = wid >> 3, wn = wid & 7;
    const int jp = wn * 4 + (lane & 3);
    __half2 bb2[5];
    load_common(smem, bt, bb2, jp, B_OFF);
    int* sidx = (int*)(smem + IDX_OFF);
    const int b = blockIdx.x;
    if (tid < 511) sidx[tid] = x_idx[b * NTREE + tid];

    fill_a_noidx(smem, 0, g_h[1] + (size_t)b * 512 * 64);
    __syncthreads();
#pragma unroll
    for (int tt = 0; tt < 2; ++tt) {
        uint32_t acc[4][5][2] = {};
        do_mma(smem, sb, acc, 128, wm, wn, lane, B_OFF);
        __syncthreads();
        if (tt == 0)
            fill_a_noidx(smem, 0, g_h[1] + (size_t)(b * 512 + 256) * 64);
        epi_top(smem, sidx + 255 + tt * 128, acc, 128,
                g_c[1] + (size_t)(b * 512 + tt * 256) * 64,
                0, BUF_SZ, tt * 64, bb2, wm, jp, lane);
        __syncthreads();
    }

    int p = 1;
#pragma unroll
    for (int d = 7; d >= 0; --d) {
        int n = 1 << d;
        uint32_t acc[4][5][2] = {};
        do_mma(smem, sb + p * BUF_SZ, acc, n, wm, wn, lane, B_OFF);
        epi_top(smem, sidx + (n - 1), acc, n, (const __half*)0,
                p * BUF_SZ + CB_OFF, (p ^ 1) * BUF_SZ, 0, bb2, wm, jp, lane);
        __syncthreads();
        p ^= 1;
    }

    // ---- head (scratch in buf1; root h in buf0 A row 0)
    float* sh = (float*)(smem + BUF_SZ);
    float* sf1 = sh + 64;
    float* sfeat = sf1 + 64;
    float* slog = sfeat + 128;
    float* sinv = slog + 20;
    const __half* hroot = (const __half*)smem;
    int t = tid;
    if (t < 64) sh[t] = __half2float(hroot[t]);
    __syncthreads();
    if (t < 64) {
        float a = 0.f;
        for (int k = 0; k < 64; ++k) a += sh[k] * W1[k * 64 + t];
        sf1[t] = fmaxf(a + b1[t], 0.f);
    }
    __syncthreads();
    if (t < 64) {
        float f = 0.f;
        for (int k = 0; k < 64; ++k) f += sf1[k] * W2[k * 64 + t];
        sfeat[t] = f + b2[t];
    }
    __syncthreads();
    if (t < 64) {
        float gi = 0.f, gg = 0.f, go = 0.f;
        for (int k = 0; k < 64; ++k) {
            float fk = sfeat[k];
            gi += fk * W_ih[k * 256 + t];
            gg += fk * W_ih[k * 256 + 128 + t];
            go += fk * W_ih[k * 256 + 192 + t];
        }
        gi += b_lstm[t];
        gg += b_lstm[128 + t];
        go += b_lstm[192 + t];
        float cg = (1.f / (1.f + expf(-gi))) * tanhf(gg);
        sfeat[64 + t] = (1.f / (1.f + expf(-go))) * tanhf(cg);
    }
    __syncthreads();
    if (t < 20) {
        float l = 0.f;
        for (int dd = 0; dd < 128; ++dd) l += sfeat[dd] * actorW[dd * 20 + t];
        l = logf(vm[t]) + l * vm[t] + actorb[t] * vm[t];
        slog[t] = l / 3.0f;
    }
    __syncthreads();
    if (t == 0) {
        float mx = slog[0];
        for (int k = 1; k < 20; ++k) mx = fmaxf(mx, slog[k]);
        float s = 0.f;
        for (int k = 0; k < 20; ++k) {
            float e = expf(slog[k] - mx);
            slog[k] = e;
            s += e;
        }
        sinv[0] = 1.f / s;
    }
    __syncthreads();
    if (t < 20) out[b * 20 + t] = slog[t] * sinv[0];
}

extern "C" void kernel_launch(void* const* d_in, const int* in_sizes, int n_in,
                              void* d_out, int out_size) {
    const int*   x_idx  = (const int*)d_in[0];
    const float* vm     = (const float*)d_in[1];
    const float* Wx     = (const float*)d_in[2];
    const float* Ua     = (const float*)d_in[3];
    const float* Ub     = (const float*)d_in[4];
    const float* bt     = (const float*)d_in[5];
    const float* W_ih   = (const float*)d_in[6];
    const float* b_lstm = (const float*)d_in[8];
    const float* W1     = (const float*)d_in[9];
    const float* b1     = (const float*)d_in[10];
    const float* W2     = (const float*)d_in[11];
    const float* b2     = (const float*)d_in[12];
    const float* actorW = (const float*)d_in[13];
    const float* actorb = (const float*)d_in[14];
    float* out = (float*)d_out;

    cudaFuncSetAttribute(level109, cudaFuncAttributeMaxDynamicSharedMemorySize, SMEM_F);
    cudaFuncSetAttribute(top_mma, cudaFuncAttributeMaxDynamicSharedMemorySize, SMEM_TOTAL);

    prep_kernel<<<80, 256>>>(Ua, Ub, Wx, bt);
    level109<<<152, NT, SMEM_F>>>(x_idx, bt);
    top_mma<<<BSZ, NT, SMEM_TOTAL>>>(x_idx, bt, W1, b1, W2, b2, W_ih, b_lstm,
                                     actorW, actorb, vm, out);
}